// round 7
// baseline (speedup 1.0000x reference)
#include <cuda_runtime.h>

#define B_SZ   16384
#define T_SZ   79
#define H_SZ   256
#define CTA_ROWS 64
#define NTHREADS 256
#define NCTAS  (B_SZ / CTA_ROWS)   // 256

typedef unsigned long long ull;

// ---- packed f32x2 helpers (Blackwell FFMA2; only reachable via PTX f32x2) ----
__device__ __forceinline__ ull dup2(float x) {
    ull r; asm("mov.b64 %0, {%1, %1};" : "=l"(r) : "f"(x)); return r;
}
__device__ __forceinline__ ull fma2(ull a, ull b, ull c) {
    ull d; asm("fma.rn.f32x2 %0, %1, %2, %3;" : "=l"(d) : "l"(a), "l"(b), "l"(c)); return d;
}
__device__ __forceinline__ void unpk2(ull v, float &x, float &y) {
    asm("mov.b64 {%0, %1}, %2;" : "=f"(x), "=f"(y) : "l"(v));
}

// Hs layout: column j (0..255) x 64 rows as 16 float4 row-groups, XOR swizzle
// so the transposed store of new h is 4-way instead of 32-way conflicted.
// GEMM-side reads are warp-broadcast -> conflict-free.
__device__ __forceinline__ int hs_idx(int j, int g /*float4 group 0..15*/) {
    return j * 64 + ((g ^ ((j >> 2) & 15)) << 2);
}

// Rank-1 update of the 8x8 thread tile: U operands arrive pre-packed (no pk movs).
__device__ __forceinline__ void mma_k(const float4 &h0, const float4 &h1,
                                      const ulonglong2 &ua, const ulonglong2 &ub,
                                      ull accA[8][2], ull accB[8][2]) {
    float hv[8] = {h0.x, h0.y, h0.z, h0.w, h1.x, h1.y, h1.z, h1.w};
#pragma unroll
    for (int r = 0; r < 8; ++r) {
        ull d = dup2(hv[r]);
        accA[r][0] = fma2(d, ua.x, accA[r][0]);
        accA[r][1] = fma2(d, ua.y, accA[r][1]);
        accB[r][0] = fma2(d, ub.x, accB[r][0]);
        accB[r][1] = fma2(d, ub.y, accB[r][1]);
    }
}

// acc(8x256 thread tile) += h(64x256 in smem) @ M(256x256 row-major).
// Distance-1 prefetch on BOTH the global M stream (L2 ~234-262 cyc) and the
// smem h stream (LDS 29 cyc) so neither dependency is exposed at issue time.
// NOTE: row stride in ulonglong2 (16B) units is 256*4/16 = 64.  (R5 bug: used 32.)
#define M_ROW_U2 64
__device__ __forceinline__ void gemm256(const float* __restrict__ M,
                                        const float* __restrict__ Hs,
                                        int tx, int ty,
                                        ull accA[8][2], ull accB[8][2]) {
    const int ga = 2 * ty, gb = 2 * ty + 1;
    const ulonglong2* Ma = reinterpret_cast<const ulonglong2*>(M + 4 * tx);
    const ulonglong2* Mb = reinterpret_cast<const ulonglong2*>(M + 128 + 4 * tx);
    ulonglong2 ua = Ma[0];
    ulonglong2 ub = Mb[0];
    float4 h0 = *reinterpret_cast<const float4*>(Hs + hs_idx(0, ga));
    float4 h1 = *reinterpret_cast<const float4*>(Hs + hs_idx(0, gb));
#pragma unroll 8
    for (int k = 0; k < H_SZ - 1; ++k) {
        ulonglong2 nua = Ma[(k + 1) * M_ROW_U2];
        ulonglong2 nub = Mb[(k + 1) * M_ROW_U2];
        float4 nh0 = *reinterpret_cast<const float4*>(Hs + hs_idx(k + 1, ga));
        float4 nh1 = *reinterpret_cast<const float4*>(Hs + hs_idx(k + 1, gb));
        mma_k(h0, h1, ua, ub, accA, accB);
        ua = nua; ub = nub; h0 = nh0; h1 = nh1;
    }
    mma_k(h0, h1, ua, ub, accA, accB);  // k = 255
}

__device__ __forceinline__ void init_acc(ull accA[8][2], ull accB[8][2],
                                         const float* __restrict__ bias,
                                         const float* __restrict__ W_in,
                                         const float* __restrict__ xs,
                                         int tx, int ty, bool withX) {
    ulonglong2 bA = *reinterpret_cast<const ulonglong2*>(bias + 4 * tx);
    ulonglong2 bB = *reinterpret_cast<const ulonglong2*>(bias + 128 + 4 * tx);
#pragma unroll
    for (int r = 0; r < 8; ++r) {
        accA[r][0] = bA.x; accA[r][1] = bA.y;
        accB[r][0] = bB.x; accB[r][1] = bB.y;
    }
    if (withX) {
#pragma unroll
        for (int f = 0; f < 3; ++f) {
            ulonglong2 wA = *reinterpret_cast<const ulonglong2*>(W_in + f * H_SZ + 4 * tx);
            ulonglong2 wB = *reinterpret_cast<const ulonglong2*>(W_in + f * H_SZ + 128 + 4 * tx);
#pragma unroll
            for (int r = 0; r < 8; ++r) {
                ull d = dup2(xs[f * CTA_ROWS + ty * 8 + r]);
                accA[r][0] = fma2(d, wA.x, accA[r][0]);
                accA[r][1] = fma2(d, wA.y, accA[r][1]);
                accB[r][0] = fma2(d, wB.x, accB[r][0]);
                accB[r][1] = fma2(d, wB.y, accB[r][1]);
            }
        }
    }
}

// relu + transpose-write new h into Hs (new h value for output column c).
__device__ __forceinline__ void store_h(float* __restrict__ Hs, int tx, int ty,
                                        ull accA[8][2], ull accB[8][2]) {
    const int g0 = 2 * ty, g1 = 2 * ty + 1;
#pragma unroll
    for (int half = 0; half < 2; ++half) {
        ull (*acc)[2] = half ? accB : accA;
        int c0 = half * 128 + 4 * tx;
#pragma unroll
        for (int cp = 0; cp < 2; ++cp) {     // column pair within the 4
            float ve[8], vo[8];
#pragma unroll
            for (int r = 0; r < 8; ++r) {
                float lo, hi; unpk2(acc[r][cp], lo, hi);
                ve[r] = fmaxf(lo, 0.0f);
                vo[r] = fmaxf(hi, 0.0f);
            }
            int ce = c0 + 2 * cp, co = ce + 1;
            *reinterpret_cast<float4*>(Hs + hs_idx(ce, g0)) = make_float4(ve[0], ve[1], ve[2], ve[3]);
            *reinterpret_cast<float4*>(Hs + hs_idx(ce, g1)) = make_float4(ve[4], ve[5], ve[6], ve[7]);
            *reinterpret_cast<float4*>(Hs + hs_idx(co, g0)) = make_float4(vo[0], vo[1], vo[2], vo[3]);
            *reinterpret_cast<float4*>(Hs + hs_idx(co, g1)) = make_float4(vo[4], vo[5], vo[6], vo[7]);
        }
    }
}

__global__ void __launch_bounds__(NTHREADS, 2)
rnn_persistent_kernel(const float* __restrict__ x0, const float* __restrict__ x1,
                      const float* __restrict__ x2, const float* __restrict__ W_in,
                      const float* __restrict__ U,  const float* __restrict__ b_rnn,
                      const float* __restrict__ W_d, const float* __restrict__ b_d,
                      float* __restrict__ out) {
    extern __shared__ float sm[];
    float* Hs = sm;                       // 256 * 64 floats (swizzled h state)
    float* xs = sm + H_SZ * CTA_ROWS;     // 3 * 64 floats (this step's raw x)

    const int tid = threadIdx.x;
    const int tx = tid & 31;
    const int ty = tid >> 5;
    const int row_base = blockIdx.x * CTA_ROWS;

    // h0 = 0
    for (int i = tid; i < H_SZ * CTA_ROWS; i += NTHREADS) Hs[i] = 0.0f;

    // cross-step x prefetch: thread (f, r) owns one x value per step
    const bool xact = tid < 3 * CTA_ROWS;
    const float* xptr = nullptr;
    float xv = 0.0f;
    if (xact) {
        int f = tid >> 6, r = tid & 63;
        const float* xb = (f == 0) ? x0 : (f == 1) ? x1 : x2;
        xptr = xb + (size_t)(row_base + r) * T_SZ;
        xv = xptr[T_SZ - 1];  // step t=0 reads tt = T-1
    }

    ull accA[8][2], accB[8][2];

    for (int t = 0; t < T_SZ; ++t) {
        if (xact) xs[tid] = xv;   // publish this step's x
        __syncthreads();          // xs ready; also orders previous step's Hs writes
        if (xact && t + 1 < T_SZ) xv = xptr[T_SZ - 2 - t];  // prefetch next step (lands ~30K cyc later)

        init_acc(accA, accB, b_rnn, W_in, xs, tx, ty, true);  // xp_t + b_rnn
        gemm256(U, Hs, tx, ty, accA, accB);                   // + h @ U
        __syncthreads();                                      // all Hs reads done
        store_h(Hs, tx, ty, accA, accB);                      // h = relu(...)
    }
    __syncthreads();

    // out = hT @ W_d + b_d  (no relu)
    init_acc(accA, accB, b_d, W_in, xs, tx, ty, false);
    gemm256(W_d, Hs, tx, ty, accA, accB);
#pragma unroll
    for (int r = 0; r < 8; ++r) {
        float* o = out + (size_t)(row_base + ty * 8 + r) * H_SZ;
        // acc ulls are already {c, c+1} packed in column order -> store directly
        *reinterpret_cast<ulonglong2*>(o + 4 * tx)       = make_ulonglong2(accA[r][0], accA[r][1]);
        *reinterpret_cast<ulonglong2*>(o + 128 + 4 * tx) = make_ulonglong2(accB[r][0], accB[r][1]);
    }
}

extern "C" void kernel_launch(void* const* d_in, const int* in_sizes, int n_in,
                              void* d_out, int out_size) {
    (void)in_sizes; (void)n_in; (void)out_size;
    const float* x0    = (const float*)d_in[0];
    const float* x1    = (const float*)d_in[1];
    const float* x2    = (const float*)d_in[2];
    const float* W_in  = (const float*)d_in[3];
    const float* U     = (const float*)d_in[4];
    const float* b_rnn = (const float*)d_in[5];
    const float* W_d   = (const float*)d_in[6];
    const float* b_d   = (const float*)d_in[7];
    float* out = (float*)d_out;

    const int smem_bytes = (H_SZ * CTA_ROWS + 3 * CTA_ROWS) * (int)sizeof(float);  // 66304
    cudaFuncSetAttribute(rnn_persistent_kernel,
                         cudaFuncAttributeMaxDynamicSharedMemorySize, smem_bytes);

    rnn_persistent_kernel<<<NCTAS, NTHREADS, smem_bytes>>>(
        x0, x1, x2, W_in, U, b_rnn, W_d, b_d, out);
}

// round 9
// speedup vs baseline: 1.5245x; 1.5245x over previous
#include <cuda_runtime.h>
#include <cuda_bf16.h>
#include <cstdint>

#define T_SZ   79
#define HDIM   256
#define MROWS  128
#define NTH    512
#define NCTAS  128            // 128 CTAs * 128 rows = 16384

// ---- smem layout (bytes) ----
#define SM_A    0             // A_hi [128][512B], A_lo at +65536   (h splits, k=0..255)
#define SM_AX   131072        // Ax_hi [128][48B], Ax_lo at +6144   (x-chunk, k16)
#define SM_B    143360        // 3 bufs * 24576 (hi 12288 + lo 12288), 48B padded n-rows
#define SM_BD   217088        // b_d 256 f
#define SM_TOT  218112

// ---- pre-split, transposed, chunk-contiguous B images ----
// layout: [chunk][n (256)][k16 (16)] bf16, 32B per n-row, 8KB per chunk
__device__ __align__(16) unsigned char g_Uimg[2][17 * 8192];  // chunks 0-15: U, 16: [W_in;b_rnn]
__device__ __align__(16) unsigned char g_Wimg[2][16 * 8192];  // W_d

__global__ void prep_kernel(const float* __restrict__ U, const float* __restrict__ W_in,
                            const float* __restrict__ b_rnn, const float* __restrict__ W_d) {
    int idx = blockIdx.x * blockDim.x + threadIdx.x;
    float val;
    unsigned char* dh;
    unsigned char* dl;
    if (idx < 17 * 4096) {
        int c = idx >> 12, rem = idx & 4095, n = rem >> 4, kk = rem & 15;
        if (c < 16)      val = U[(c * 16 + kk) * 256 + n];
        else if (kk < 3) val = W_in[kk * 256 + n];
        else if (kk == 3) val = b_rnn[n];
        else             val = 0.0f;
        int off = c * 8192 + n * 32 + kk * 2;
        dh = g_Uimg[0] + off; dl = g_Uimg[1] + off;
    } else if (idx < 17 * 4096 + 16 * 4096) {
        int j = idx - 17 * 4096;
        int c = j >> 12, n = (j & 4095) >> 4, kk = j & 15;
        val = W_d[(c * 16 + kk) * 256 + n];
        int off = c * 8192 + n * 32 + kk * 2;
        dh = g_Wimg[0] + off; dl = g_Wimg[1] + off;
    } else return;
    __nv_bfloat16 h = __float2bfloat16_rn(val);
    __nv_bfloat16 l = __float2bfloat16_rn(val - __bfloat162float(h));
    *(unsigned short*)dh = *(unsigned short*)&h;
    *(unsigned short*)dl = *(unsigned short*)&l;
}

// ---- PTX helpers (all plain sm_80+ features: compile on bare sm_103 target) ----
__device__ __forceinline__ uint32_t smem_u32(const void* p) {
    uint32_t a;
    asm("{ .reg .u64 t; cvta.to.shared.u64 t, %1; cvt.u32.u64 %0, t; }" : "=r"(a) : "l"(p));
    return a;
}
__device__ __forceinline__ void ldsm4(uint32_t r[4], uint32_t addr) {
    asm volatile("ldmatrix.sync.aligned.m8n8.x4.shared.b16 {%0,%1,%2,%3}, [%4];"
                 : "=r"(r[0]), "=r"(r[1]), "=r"(r[2]), "=r"(r[3]) : "r"(addr));
}
__device__ __forceinline__ void mma16816(float d[4], const uint32_t a[4], const uint32_t b[2]) {
    asm volatile("mma.sync.aligned.m16n8k16.row.col.f32.bf16.bf16.f32 "
                 "{%0,%1,%2,%3}, {%4,%5,%6,%7}, {%8,%9}, {%0,%1,%2,%3};"
                 : "+f"(d[0]), "+f"(d[1]), "+f"(d[2]), "+f"(d[3])
                 : "r"(a[0]), "r"(a[1]), "r"(a[2]), "r"(a[3]), "r"(b[0]), "r"(b[1]));
}
__device__ __forceinline__ void cpa16(uint32_t dst, const unsigned char* src) {
    asm volatile("cp.async.cg.shared.global [%0], [%1], 16;" :: "r"(dst), "l"(src) : "memory");
}
#define CP_COMMIT() asm volatile("cp.async.commit_group;" ::: "memory")
#define CP_WAIT1()  asm volatile("cp.async.wait_group 1;" ::: "memory")
#define CP_WAIT0()  asm volatile("cp.async.wait_group 0;" ::: "memory")

struct TileCtx { uint32_t sb; int tid, lane, m0, nb; };

// stage one (hi+lo) B chunk into ring buffer buf = c%3; 2 cp.asyncs per thread
__device__ __forceinline__ void issue_chunk(const TileCtx& cx, const unsigned char* img_hi,
                                            const unsigned char* img_lo, int c) {
    int buf = c % 3;
#pragma unroll
    for (int s = 0; s < 2; ++s) {
        int idx = cx.tid + s * NTH;          // 0..1023
        int split = idx >> 9;
        int rem = idx & 511, row = rem >> 1, half = rem & 1;
        const unsigned char* img = split ? img_lo : img_hi;
        cpa16(cx.sb + SM_B + buf * 24576 + split * 12288 + row * 48 + half * 16,
              img + c * 8192 + row * 32 + half * 16);
    }
}

// one K16 chunk: 3 split passes (Ah*Bh + Ah*Bl + Al*Bh) into D
__device__ __forceinline__ void mma_chunk(const TileCtx& cx, float D[2][8][4], int c) {
    uint32_t Ah[2][4], Al[2][4];
    const int hb = (cx.lane >> 4) & 1;
#pragma unroll
    for (int mt = 0; mt < 2; ++mt) {
        int mrow = cx.m0 + mt * 16 + (cx.lane & 15);
        uint32_t a0;
        if (c < 16) {
            uint32_t boff = (uint32_t)(c * 32 + hb * 16) ^ ((mrow & 7) << 4);
            a0 = cx.sb + SM_A + mrow * 512 + boff;
            ldsm4(Ah[mt], a0);
            ldsm4(Al[mt], a0 + 65536);
        } else {
            a0 = cx.sb + SM_AX + mrow * 48 + hb * 16;
            ldsm4(Ah[mt], a0);
            ldsm4(Al[mt], a0 + 6144);
        }
    }
    const uint32_t bB = cx.sb + SM_B + (c % 3) * 24576;
    const int nB = cx.nb + ((cx.lane >> 4) & 1) * 8 + (cx.lane & 7);
    const int hbB = ((cx.lane >> 3) & 1) * 16;
#pragma unroll
    for (int pass = 0; pass < 3; ++pass) {
        uint32_t (*A)[4] = (pass == 2) ? Al : Ah;
        uint32_t bsb = bB + ((pass == 1) ? 12288 : 0);
#pragma unroll
        for (int ng = 0; ng < 4; ++ng) {
            uint32_t B4[4];
            ldsm4(B4, bsb + (nB + ng * 16) * 48 + hbB);
#pragma unroll
            for (int mt = 0; mt < 2; ++mt) {
                mma16816(D[mt][2 * ng],     A[mt], B4);
                mma16816(D[mt][2 * ng + 1], A[mt], B4 + 2);
            }
        }
    }
}

// triple-buffered chunk loop [c0, cend)
__device__ __forceinline__ void run_chunks(const TileCtx& cx, float D[2][8][4],
                                           const unsigned char* ih, const unsigned char* il,
                                           int c0, int cend) {
    issue_chunk(cx, ih, il, c0);
    CP_COMMIT();
    for (int c = c0; c < cend; ++c) {
        if (c + 1 < cend) issue_chunk(cx, ih, il, c + 1);
        CP_COMMIT();
        if (c + 1 < cend) CP_WAIT1(); else CP_WAIT0();
        __syncthreads();          // chunk c staged; also fences A/Ax writes & buffer reuse
        mma_chunk(cx, D, c);
    }
}

__global__ void __launch_bounds__(NTH, 1)
rnn_mma_kernel(const float* __restrict__ x0, const float* __restrict__ x1,
               const float* __restrict__ x2, const float* __restrict__ b_d,
               float* __restrict__ out) {
    extern __shared__ __align__(1024) unsigned char smem[];
    TileCtx cx;
    cx.sb = smem_u32(smem);
    cx.tid = threadIdx.x;
    cx.lane = cx.tid & 31;
    const int w = cx.tid >> 5;
    cx.m0 = (w & 3) * 32;
    cx.nb = (w >> 2) * 64;
    const int row_base = blockIdx.x * MROWS;

    // init: zero Ax region, bias column (k=3) = 1.0 in hi, b_d to smem
    for (int i = cx.tid; i < 12288 / 4; i += NTH) ((uint32_t*)(smem + SM_AX))[i] = 0;
    __syncthreads();
    if (cx.tid < 128) *(unsigned short*)(smem + SM_AX + cx.tid * 48 + 6) = 0x3F80;
    if (cx.tid < 256) ((float*)(smem + SM_BD))[cx.tid] = b_d[cx.tid];

    // cross-step x prefetch: thread (row, f) owns one value per step
    const int xrow = cx.tid >> 2, xf = cx.tid & 3;
    const bool xact = (xf < 3);
    const float* xbase = (xf == 0) ? x0 : (xf == 1) ? x1 : x2;
    float xv = 0.0f;
    if (xact) xv = xbase[(size_t)(row_base + xrow) * T_SZ + (T_SZ - 1)];

    float D[2][8][4];

    for (int t = 0; t < T_SZ; ++t) {
        // publish this step's x-chunk (A cols 0-2), split bf16
        if (xact) {
            __nv_bfloat16 h = __float2bfloat16_rn(xv);
            __nv_bfloat16 l = __float2bfloat16_rn(xv - __bfloat162float(h));
            *(unsigned short*)(smem + SM_AX + xrow * 48 + xf * 2) = *(unsigned short*)&h;
            *(unsigned short*)(smem + SM_AX + 6144 + xrow * 48 + xf * 2) = *(unsigned short*)&l;
        }
        if (xact && t + 1 < T_SZ)
            xv = xbase[(size_t)(row_base + xrow) * T_SZ + (T_SZ - 2 - t)];  // lands next step

#pragma unroll
        for (int mt = 0; mt < 2; ++mt)
#pragma unroll
            for (int nt = 0; nt < 8; ++nt)
#pragma unroll
                for (int e = 0; e < 4; ++e) D[mt][nt][e] = 0.0f;

        // t=0: h=0, only the x-chunk contributes
        run_chunks(cx, D, g_Uimg[0], g_Uimg[1], (t == 0) ? 16 : 0, 17);

        __syncthreads();  // all ldmatrix reads of A done before rewrite

        // epilogue: h = relu(D); split -> A hi/lo smem (swizzled)
#pragma unroll
        for (int mt = 0; mt < 2; ++mt) {
            int mA = cx.m0 + mt * 16 + (cx.lane >> 2);
#pragma unroll
            for (int nt = 0; nt < 8; ++nt) {
                int n = cx.nb + nt * 8 + 2 * (cx.lane & 3);
#pragma unroll
                for (int half = 0; half < 2; ++half) {   // half1 = rows +8
                    int m = mA + half * 8;
                    float v0 = fmaxf(D[mt][nt][2 * half], 0.0f);
                    float v1 = fmaxf(D[mt][nt][2 * half + 1], 0.0f);
                    uint32_t hp;
                    asm("cvt.rn.bf16x2.f32 %0, %1, %2;" : "=r"(hp) : "f"(v1), "f"(v0));
                    float h0 = __uint_as_float(hp << 16);
                    float h1 = __uint_as_float(hp & 0xFFFF0000u);
                    uint32_t lp;
                    asm("cvt.rn.bf16x2.f32 %0, %1, %2;" : "=r"(lp) : "f"(v1 - h1), "f"(v0 - h0));
                    uint32_t off = (uint32_t)(2 * n) ^ ((m & 7) << 4);
                    *(uint32_t*)(smem + SM_A + m * 512 + off) = hp;
                    *(uint32_t*)(smem + SM_A + 65536 + m * 512 + off) = lp;
                }
            }
        }
    }

    // final GEMM: out = hT @ W_d + b_d
#pragma unroll
    for (int mt = 0; mt < 2; ++mt)
#pragma unroll
        for (int nt = 0; nt < 8; ++nt)
#pragma unroll
            for (int e = 0; e < 4; ++e) D[mt][nt][e] = 0.0f;
    run_chunks(cx, D, g_Wimg[0], g_Wimg[1], 0, 16);

    const float* bd = (const float*)(smem + SM_BD);
#pragma unroll
    for (int mt = 0; mt < 2; ++mt) {
        int mA = cx.m0 + mt * 16 + (cx.lane >> 2);
#pragma unroll
        for (int nt = 0; nt < 8; ++nt) {
            int n = cx.nb + nt * 8 + 2 * (cx.lane & 3);
            float b0 = bd[n], b1 = bd[n + 1];
#pragma unroll
            for (int half = 0; half < 2; ++half) {
                int m = mA + half * 8;
                float2 o = make_float2(D[mt][nt][2 * half] + b0, D[mt][nt][2 * half + 1] + b1);
                *(float2*)(out + (size_t)(row_base + m) * HDIM + n) = o;
            }
        }
    }
}

extern "C" void kernel_launch(void* const* d_in, const int* in_sizes, int n_in,
                              void* d_out, int out_size) {
    (void)in_sizes; (void)n_in; (void)out_size;
    const float* x0    = (const float*)d_in[0];
    const float* x1    = (const float*)d_in[1];
    const float* x2    = (const float*)d_in[2];
    const float* W_in  = (const float*)d_in[3];
    const float* U     = (const float*)d_in[4];
    const float* b_rnn = (const float*)d_in[5];
    const float* W_d   = (const float*)d_in[6];
    const float* b_d   = (const float*)d_in[7];
    float* out = (float*)d_out;

    prep_kernel<<<528, 256>>>(U, W_in, b_rnn, W_d);

    cudaFuncSetAttribute(rnn_mma_kernel,
                         cudaFuncAttributeMaxDynamicSharedMemorySize, SM_TOT);
    rnn_mma_kernel<<<NCTAS, NTH, SM_TOT>>>(x0, x1, x2, b_d, out);
}

// round 11
// speedup vs baseline: 2.6734x; 1.7537x over previous
#include <cuda_runtime.h>
#include <cuda_bf16.h>
#include <cstdint>

#define T_SZ   79
#define HDIM   256
#define MROWS  128
#define NTH    512
#define NCTAS  128

#define N_SCAN_CHUNKS (T_SZ * 16)            // 1264
#define TOTAL_CHUNKS  (N_SCAN_CHUNKS + 16)   // 1280 (+ W_d)
#define NPAIRS        (TOTAL_CHUNKS / 2)     // 640

// ---- smem layout (bytes) ----
#define SM_A     0          // A hi [128][512B] swizzled, lo at +65536
#define SM_AX    131072     // x-chunk A: hi [128][32B], lo at +4096
#define SM_WIN   139264     // resident [W_in;b_rnn] B: hi [256][32B], lo at +8192
#define SM_B     155648     // ring 4 slots x 16384 (hi 8192 + lo 8192), 32B rows + half-swizzle
#define SM_BD    221184     // b_d 256 f
#define SM_TOT   222208

// ---- pre-split, transposed, chunk-contiguous B images ----
// streamed chunks (c<16 of U, all of W_d): [c][n(256)][32B row], halves XOR-swizzled
// chunk 16 of U image = [W_in;b_rnn], stored UNswizzled (read directly, not via ring)
__device__ __align__(16) unsigned char g_Uimg[2][17 * 8192];
__device__ __align__(16) unsigned char g_Wimg[2][16 * 8192];

__global__ void prep_kernel(const float* __restrict__ U, const float* __restrict__ W_in,
                            const float* __restrict__ b_rnn, const float* __restrict__ W_d) {
    int idx = blockIdx.x * blockDim.x + threadIdx.x;
    float val;
    unsigned char *dh, *dl;
    if (idx < 17 * 4096) {
        int c = idx >> 12, rem = idx & 4095, n = rem >> 4, kk = rem & 15;
        if (c < 16)       val = U[(c * 16 + kk) * 256 + n];
        else if (kk < 3)  val = W_in[kk * 256 + n];
        else if (kk == 3) val = b_rnn[n];
        else              val = 0.0f;
        int half = kk >> 3;
        if (c < 16) half ^= (n >> 2) & 1;               // bake ldmatrix swizzle
        int off = c * 8192 + n * 32 + half * 16 + (kk & 7) * 2;
        dh = g_Uimg[0] + off; dl = g_Uimg[1] + off;
    } else if (idx < 17 * 4096 + 16 * 4096) {
        int j = idx - 17 * 4096;
        int c = j >> 12, n = (j & 4095) >> 4, kk = j & 15;
        val = W_d[(c * 16 + kk) * 256 + n];
        int half = (kk >> 3) ^ ((n >> 2) & 1);
        int off = c * 8192 + n * 32 + half * 16 + (kk & 7) * 2;
        dh = g_Wimg[0] + off; dl = g_Wimg[1] + off;
    } else return;
    __nv_bfloat16 h = __float2bfloat16_rn(val);
    __nv_bfloat16 l = __float2bfloat16_rn(val - __bfloat162float(h));
    *(unsigned short*)dh = *(unsigned short*)&h;
    *(unsigned short*)dl = *(unsigned short*)&l;
}

// ---- PTX helpers (only primitives proven in the passing R9 kernel) ----
__device__ __forceinline__ uint32_t smem_u32(const void* p) {
    uint32_t a;
    asm("{ .reg .u64 t; cvta.to.shared.u64 t, %1; cvt.u32.u64 %0, t; }" : "=r"(a) : "l"(p));
    return a;
}
__device__ __forceinline__ void ldsm4(uint32_t r[4], uint32_t addr) {
    asm volatile("ldmatrix.sync.aligned.m8n8.x4.shared.b16 {%0,%1,%2,%3}, [%4];"
                 : "=r"(r[0]), "=r"(r[1]), "=r"(r[2]), "=r"(r[3]) : "r"(addr));
}
__device__ __forceinline__ void mma16816(float d[4], const uint32_t a[4], const uint32_t b[2]) {
    asm volatile("mma.sync.aligned.m16n8k16.row.col.f32.bf16.bf16.f32 "
                 "{%0,%1,%2,%3}, {%4,%5,%6,%7}, {%8,%9}, {%0,%1,%2,%3};"
                 : "+f"(d[0]), "+f"(d[1]), "+f"(d[2]), "+f"(d[3])
                 : "r"(a[0]), "r"(a[1]), "r"(a[2]), "r"(a[3]), "r"(b[0]), "r"(b[1]));
}
__device__ __forceinline__ void cpa16(uint32_t dst, const unsigned char* src) {
    asm volatile("cp.async.cg.shared.global [%0], [%1], 16;" :: "r"(dst), "l"(src) : "memory");
}
#define CP_COMMIT() asm volatile("cp.async.commit_group;" ::: "memory")
#define CP_WAIT0()  asm volatile("cp.async.wait_group 0;" ::: "memory")

struct TileCtx { uint32_t sb; int tid, lane, m0, nb; };

// stage pair p (chunks 2p, 2p+1) into ring slots (g&3); verbatim copy (swizzle pre-baked)
__device__ __forceinline__ void issue_pair(const TileCtx& cx, int p) {
    int g0 = 2 * p;
#pragma unroll
    for (int s = 0; s < 4; ++s) {
        int idx = cx.tid + s * NTH;              // 0..2047
        int g = g0 + (idx >> 10);
        int cid = g & 15, slot = g & 3;
        int split = (idx >> 9) & 1;
        int off = (idx & 511) * 16;
        const unsigned char* img = (g < N_SCAN_CHUNKS) ? g_Uimg[split] : g_Wimg[split];
        cpa16(cx.sb + SM_B + slot * 16384 + split * 8192 + off, img + cid * 8192 + off);
    }
}

// one K16 chunk from ring slot: 3 passes (Ah*Bh, Ah*Bl, Al*Bh)
__device__ __forceinline__ void mma_chunk(const TileCtx& cx, float D[2][8][4], int c, int slot) {
    uint32_t Ah[2][4], Al[2][4];
    const int hb = (cx.lane >> 4) & 1;
#pragma unroll
    for (int mt = 0; mt < 2; ++mt) {
        int mrow = cx.m0 + mt * 16 + (cx.lane & 15);
        uint32_t boff = (uint32_t)(c * 32 + hb * 16) ^ ((mrow & 7) << 4);
        uint32_t a0 = cx.sb + SM_A + mrow * 512 + boff;
        ldsm4(Ah[mt], a0);
        ldsm4(Al[mt], a0 + 65536);
    }
    const uint32_t bB = cx.sb + SM_B + slot * 16384;
    const int nB = cx.nb + ((cx.lane >> 4) & 1) * 8 + (cx.lane & 7);
    const uint32_t hbB = (uint32_t)(((cx.lane >> 3) & 1) * 16);
#pragma unroll
    for (int pass = 0; pass < 3; ++pass) {
        uint32_t (*A)[4] = (pass == 2) ? Al : Ah;
        uint32_t bsb = bB + ((pass == 1) ? 8192 : 0);
#pragma unroll
        for (int ng = 0; ng < 4; ++ng) {
            uint32_t nr = (uint32_t)(nB + ng * 16);
            uint32_t B4[4];
            ldsm4(B4, bsb + nr * 32 + (hbB ^ ((nr & 4) << 2)));   // half-swizzled rows
#pragma unroll
            for (int mt = 0; mt < 2; ++mt) {
                mma16816(D[mt][2 * ng],     A[mt], B4);
                mma16816(D[mt][2 * ng + 1], A[mt], B4 + 2);
            }
        }
    }
}

// x-chunk: A from SM_AX, B = resident [W_in;b_rnn] (both plain 32B rows; once/step)
__device__ __forceinline__ void mma_xchunk(const TileCtx& cx, float D[2][8][4]) {
    uint32_t Ah[2][4], Al[2][4];
    const int hb = (cx.lane >> 4) & 1;
#pragma unroll
    for (int mt = 0; mt < 2; ++mt) {
        int mrow = cx.m0 + mt * 16 + (cx.lane & 15);
        uint32_t a0 = cx.sb + SM_AX + mrow * 32 + hb * 16;
        ldsm4(Ah[mt], a0);
        ldsm4(Al[mt], a0 + 4096);
    }
    const int nB = cx.nb + ((cx.lane >> 4) & 1) * 8 + (cx.lane & 7);
    const uint32_t hbB = (uint32_t)(((cx.lane >> 3) & 1) * 16);
#pragma unroll
    for (int pass = 0; pass < 3; ++pass) {
        uint32_t (*A)[4] = (pass == 2) ? Al : Ah;
        uint32_t bsb = cx.sb + SM_WIN + ((pass == 1) ? 8192 : 0);
#pragma unroll
        for (int ng = 0; ng < 4; ++ng) {
            uint32_t B4[4];
            ldsm4(B4, bsb + (uint32_t)(nB + ng * 16) * 32 + hbB);
#pragma unroll
            for (int mt = 0; mt < 2; ++mt) {
                mma16816(D[mt][2 * ng],     A[mt], B4);
                mma16816(D[mt][2 * ng + 1], A[mt], B4 + 2);
            }
        }
    }
}

__global__ void __launch_bounds__(NTH, 1)
rnn_mma_kernel(const float* __restrict__ x0, const float* __restrict__ x1,
               const float* __restrict__ x2, const float* __restrict__ b_d,
               float* __restrict__ out) {
    extern __shared__ __align__(1024) unsigned char smem[];
    TileCtx cx;
    cx.sb = smem_u32(smem);
    cx.tid = threadIdx.x;
    cx.lane = cx.tid & 31;
    const int w = cx.tid >> 5;
    cx.m0 = (w & 3) * 32;
    cx.nb = (w >> 2) * 64;
    const int row_base = blockIdx.x * MROWS;

    // ---- init: zero A (h0=0) and Ax ----
    for (int i = cx.tid; i < 131072 / 4; i += NTH) ((uint32_t*)(smem + SM_A))[i] = 0;
    for (int i = cx.tid; i < 8192 / 4; i += NTH) ((uint32_t*)(smem + SM_AX))[i] = 0;
    __syncthreads();
    // bias col (k=3)=1.0 in Ax-hi; b_d -> smem; resident W_in image -> smem (verbatim)
    if (cx.tid < 128) *(unsigned short*)(smem + SM_AX + cx.tid * 32 + 6) = 0x3F80;
    if (cx.tid < 256) ((float*)(smem + SM_BD))[cx.tid] = b_d[cx.tid];
    for (int i = cx.tid; i < 4096; i += NTH) {
        int split = i >> 11, off = (i & 2047) * 4;
        *(uint32_t*)(smem + SM_WIN + split * 8192 + off) =
            *(const uint32_t*)(g_Uimg[split] + 16 * 8192 + off);
    }
    // x prefetch: thread (row, f) owns one value per step; publish x(t=0) now
    const int xrow = cx.tid >> 2, xf = cx.tid & 3;
    const bool xact = (xf < 3);
    const float* xbase = (xf == 0) ? x0 : (xf == 1) ? x1 : x2;
    if (xact) {
        float v = xbase[(size_t)(row_base + xrow) * T_SZ + (T_SZ - 1)];
        __nv_bfloat16 h = __float2bfloat16_rn(v);
        __nv_bfloat16 l = __float2bfloat16_rn(v - __bfloat162float(h));
        *(unsigned short*)(smem + SM_AX + xrow * 32 + xf * 2) = *(unsigned short*)&h;
        *(unsigned short*)(smem + SM_AX + 4096 + xrow * 32 + xf * 2) = *(unsigned short*)&l;
    }
    float xv = 0.0f;
    if (xact) xv = xbase[(size_t)(row_base + xrow) * T_SZ + (T_SZ - 2)];
    __syncthreads();   // init state visible

    float D[2][8][4];
#pragma unroll
    for (int mt = 0; mt < 2; ++mt)
#pragma unroll
        for (int nt = 0; nt < 8; ++nt)
#pragma unroll
            for (int e = 0; e < 4; ++e) D[mt][nt][e] = 0.0f;

    issue_pair(cx, 0);
    CP_COMMIT();

    for (int p = 0; p < NPAIRS; ++p) {
        CP_WAIT0();          // my granules of pair p landed
        __syncthreads();     // everyone's landed; all reads of pair p-1 (and prior A) done
        if (p + 1 < NPAIRS) { issue_pair(cx, p + 1); CP_COMMIT(); }  // into pair p-1's slots

        int g0 = 2 * p;
        mma_chunk(cx, D, g0 & 15, g0 & 3);
        int g1 = g0 + 1;
        mma_chunk(cx, D, g1 & 15, g1 & 3);

        if ((g1 & 15) == 15 && g1 < N_SCAN_CHUNKS) {   // end of scan step
            int step = g1 >> 4;
            mma_xchunk(cx, D);                 // + x@W_in + b_rnn
            __syncthreads();                   // all A/Ax reads of this step done
            if (xact && step + 1 < T_SZ) {     // publish next x
                __nv_bfloat16 h = __float2bfloat16_rn(xv);
                __nv_bfloat16 l = __float2bfloat16_rn(xv - __bfloat162float(h));
                *(unsigned short*)(smem + SM_AX + xrow * 32 + xf * 2) = *(unsigned short*)&h;
                *(unsigned short*)(smem + SM_AX + 4096 + xrow * 32 + xf * 2) = *(unsigned short*)&l;
                if (step + 2 < T_SZ)
                    xv = xbase[(size_t)(row_base + xrow) * T_SZ + (T_SZ - 3 - step)];
            }
            // epilogue: h = relu(D) -> split -> A (swizzled); zero D
#pragma unroll
            for (int mt = 0; mt < 2; ++mt) {
                int mA = cx.m0 + mt * 16 + (cx.lane >> 2);
#pragma unroll
                for (int nt = 0; nt < 8; ++nt) {
                    int n = cx.nb + nt * 8 + 2 * (cx.lane & 3);
#pragma unroll
                    for (int half = 0; half < 2; ++half) {
                        int m = mA + half * 8;
                        float v0 = fmaxf(D[mt][nt][2 * half], 0.0f);
                        float v1 = fmaxf(D[mt][nt][2 * half + 1], 0.0f);
                        uint32_t hp;
                        asm("cvt.rn.bf16x2.f32 %0, %1, %2;" : "=r"(hp) : "f"(v1), "f"(v0));
                        float h0 = __uint_as_float(hp << 16);
                        float h1 = __uint_as_float(hp & 0xFFFF0000u);
                        uint32_t lp;
                        asm("cvt.rn.bf16x2.f32 %0, %1, %2;" : "=r"(lp) : "f"(v1 - h1), "f"(v0 - h0));
                        uint32_t off = (uint32_t)(2 * n) ^ ((m & 7) << 4);
                        *(uint32_t*)(smem + SM_A + m * 512 + off) = hp;
                        *(uint32_t*)(smem + SM_A + 65536 + m * 512 + off) = lp;
                    }
                }
            }
#pragma unroll
            for (int mt = 0; mt < 2; ++mt)
#pragma unroll
                for (int nt = 0; nt < 8; ++nt)
#pragma unroll
                    for (int e = 0; e < 4; ++e) D[mt][nt][e] = 0.0f;
            // no trailing sync: next iteration's __syncthreads orders A-writes before reads
        }
    }

    // ---- final output: out = D + b_d ----
    const float* bd = (const float*)(smem + SM_BD);
#pragma unroll
    for (int mt = 0; mt < 2; ++mt) {
        int mA = cx.m0 + mt * 16 + (cx.lane >> 2);
#pragma unroll
        for (int nt = 0; nt < 8; ++nt) {
            int n = cx.nb + nt * 8 + 2 * (cx.lane & 3);
            float b0 = bd[n], b1 = bd[n + 1];
#pragma unroll
            for (int half = 0; half < 2; ++half) {
                int m = mA + half * 8;
                float2 o = make_float2(D[mt][nt][2 * half] + b0, D[mt][nt][2 * half + 1] + b1);
                *(float2*)(out + (size_t)(row_base + m) * HDIM + n) = o;
            }
        }
    }
}

extern "C" void kernel_launch(void* const* d_in, const int* in_sizes, int n_in,
                              void* d_out, int out_size) {
    (void)in_sizes; (void)n_in; (void)out_size;
    const float* x0    = (const float*)d_in[0];
    const float* x1    = (const float*)d_in[1];
    const float* x2    = (const float*)d_in[2];
    const float* W_in  = (const float*)d_in[3];
    const float* U     = (const float*)d_in[4];
    const float* b_rnn = (const float*)d_in[5];
    const float* W_d   = (const float*)d_in[6];
    const float* b_d   = (const float*)d_in[7];
    float* out = (float*)d_out;

    prep_kernel<<<528, 256>>>(U, W_in, b_rnn, W_d);

    cudaFuncSetAttribute(rnn_mma_kernel,
                         cudaFuncAttributeMaxDynamicSharedMemorySize, SM_TOT);
    rnn_mma_kernel<<<NCTAS, NTH, SM_TOT>>>(x0, x1, x2, b_d, out);
}

// round 12
// speedup vs baseline: 2.9605x; 1.1074x over previous
#include <cuda_runtime.h>
#include <cuda_bf16.h>
#include <cstdint>

#define T_SZ   79
#define HDIM   256
#define MROWS  128
#define NTH    512
#define NCTAS  128

// ---- smem layout (bytes) ----
#define SM_A    0          // A hi [128][512B] swizzled, lo at +65536
#define SM_AX   131072     // x-chunk A: hi [128][32B], lo at +4096
#define SM_BD   139264     // b_d 256 f
#define SM_TOT  140288

// ---- fragment-ordered B images ----
// [chunk][G(16 n16-groups)][lane(32)][16B]: lane fragment = {frag0..3} .b32 pairs
//   frag0: n=G*16+l/4,   k=2*(l%4),(+1)   frag1: same n, k+8
//   frag2: n=G*16+8+l/4, k=2*(l%4),(+1)   frag3: n+8, k+8
// (exact mma.m16n8k16 col-B layout -> one LDG.128 per lane per n16 group)
__device__ __align__(16) unsigned char g_U2[2][17 * 8192];  // chunks 0-15: U; 16: [W_in;b_rnn]
__device__ __align__(16) unsigned char g_W2[2][16 * 8192];  // W_d

__global__ void prep_kernel(const float* __restrict__ U, const float* __restrict__ W_in,
                            const float* __restrict__ b_rnn, const float* __restrict__ W_d) {
    int idx = blockIdx.x * blockDim.x + threadIdx.x;
    if (idx >= 33 * 512) return;                 // 33 chunk-images * 16 G * 32 lanes
    int cimg = idx >> 9;                          // 0..32
    int G = (idx >> 5) & 15;
    int l = idx & 31;
    bool isU = (cimg < 17);
    int c = isU ? cimg : cimg - 17;
    uint32_t hi4[4], lo4[4];
#pragma unroll
    for (int f = 0; f < 4; ++f) {
        int n = G * 16 + (l >> 2) + ((f & 2) ? 8 : 0);
        int kk = 2 * (l & 3) + ((f & 1) ? 8 : 0);
        float v[2];
#pragma unroll
        for (int j = 0; j < 2; ++j) {
            int kq = kk + j;
            if (!isU)            v[j] = W_d[(c * 16 + kq) * 256 + n];
            else if (c < 16)     v[j] = U[(c * 16 + kq) * 256 + n];
            else if (kq < 3)     v[j] = W_in[kq * 256 + n];
            else if (kq == 3)    v[j] = b_rnn[n];
            else                 v[j] = 0.0f;
        }
        __nv_bfloat16 h0 = __float2bfloat16_rn(v[0]);
        __nv_bfloat16 h1 = __float2bfloat16_rn(v[1]);
        __nv_bfloat16 l0 = __float2bfloat16_rn(v[0] - __bfloat162float(h0));
        __nv_bfloat16 l1 = __float2bfloat16_rn(v[1] - __bfloat162float(h1));
        hi4[f] = (uint32_t)*(unsigned short*)&h0 | ((uint32_t)*(unsigned short*)&h1 << 16);
        lo4[f] = (uint32_t)*(unsigned short*)&l0 | ((uint32_t)*(unsigned short*)&l1 << 16);
    }
    int off = (c * 16 + G) * 512 + l * 16;
    unsigned char* bh = isU ? g_U2[0] : g_W2[0];
    unsigned char* bl = isU ? g_U2[1] : g_W2[1];
    *(uint4*)(bh + off) = make_uint4(hi4[0], hi4[1], hi4[2], hi4[3]);
    *(uint4*)(bl + off) = make_uint4(lo4[0], lo4[1], lo4[2], lo4[3]);
}

// ---- PTX helpers ----
__device__ __forceinline__ uint32_t smem_u32(const void* p) {
    uint32_t a;
    asm("{ .reg .u64 t; cvta.to.shared.u64 t, %1; cvt.u32.u64 %0, t; }" : "=r"(a) : "l"(p));
    return a;
}
__device__ __forceinline__ void ldsm4(uint32_t r[4], uint32_t addr) {
    asm volatile("ldmatrix.sync.aligned.m8n8.x4.shared.b16 {%0,%1,%2,%3}, [%4];"
                 : "=r"(r[0]), "=r"(r[1]), "=r"(r[2]), "=r"(r[3]) : "r"(addr));
}
__device__ __forceinline__ void mma16816(float d[4], const uint32_t a[4],
                                         uint32_t b0, uint32_t b1) {
    asm volatile("mma.sync.aligned.m16n8k16.row.col.f32.bf16.bf16.f32 "
                 "{%0,%1,%2,%3}, {%4,%5,%6,%7}, {%8,%9}, {%0,%1,%2,%3};"
                 : "+f"(d[0]), "+f"(d[1]), "+f"(d[2]), "+f"(d[3])
                 : "r"(a[0]), "r"(a[1]), "r"(a[2]), "r"(a[3]), "r"(b0), "r"(b1));
}

struct TileCtx { uint32_t sb; int tid, lane, m0, nb; };

// A fragments for chunk c (c==16 -> x-chunk from SM_AX)
__device__ __forceinline__ void loadA(const TileCtx& cx, int c,
                                      uint32_t Ah[2][4], uint32_t Al[2][4]) {
    const int hb = (cx.lane >> 4) & 1;
#pragma unroll
    for (int mt = 0; mt < 2; ++mt) {
        int mrow = cx.m0 + mt * 16 + (cx.lane & 15);
        if (c < 16) {
            uint32_t boff = (uint32_t)(c * 32 + hb * 16) ^ ((mrow & 7) << 4);
            uint32_t a0 = cx.sb + SM_A + mrow * 512 + boff;
            ldsm4(Ah[mt], a0);
            ldsm4(Al[mt], a0 + 65536);
        } else {
            uint32_t a0 = cx.sb + SM_AX + mrow * 32 + hb * 16;
            ldsm4(Ah[mt], a0);
            ldsm4(Al[mt], a0 + 4096);
        }
    }
}

// one n16 unit: 12 MMAs, Bh reused in passes 0 and 2
__device__ __forceinline__ void mma_unit(float D[2][8][4], const uint32_t Ah[2][4],
                                         const uint32_t Al[2][4],
                                         const uint4& bh, const uint4& bl, int ng) {
#pragma unroll
    for (int mt = 0; mt < 2; ++mt) {
        mma16816(D[mt][2 * ng],     Ah[mt], bh.x, bh.y);
        mma16816(D[mt][2 * ng + 1], Ah[mt], bh.z, bh.w);
    }
#pragma unroll
    for (int mt = 0; mt < 2; ++mt) {
        mma16816(D[mt][2 * ng],     Ah[mt], bl.x, bl.y);
        mma16816(D[mt][2 * ng + 1], Ah[mt], bl.z, bl.w);
    }
#pragma unroll
    for (int mt = 0; mt < 2; ++mt) {
        mma16816(D[mt][2 * ng],     Al[mt], bh.x, bh.y);
        mma16816(D[mt][2 * ng + 1], Al[mt], bh.z, bh.w);
    }
}

// stream nchunks K16 chunks; B fragments straight from global with distance-1 prefetch
__device__ __forceinline__ void stream_chunks(const TileCtx& cx, float D[2][8][4],
        const unsigned char* __restrict__ ih, const unsigned char* __restrict__ il,
        int nchunks) {
    uint32_t Ah[2][4], Al[2][4];
    const uint32_t lb = (uint32_t)((cx.nb >> 4) * 512 + cx.lane * 16);
    uint4 Bh[2], Bl[2];
    loadA(cx, 0, Ah, Al);
    Bh[0] = *(const uint4*)(ih + lb);
    Bl[0] = *(const uint4*)(il + lb);
    for (int c = 0; c < nchunks; ++c) {
        uint32_t cb = (uint32_t)c * 8192 + lb;
#pragma unroll
        for (int ng = 0; ng < 4; ++ng) {
            bool last = (c == nchunks - 1) && (ng == 3);
            if (!last) {
                uint32_t o = (ng < 3) ? (cb + (ng + 1) * 512) : (cb + 8192);
                Bh[(ng + 1) & 1] = *(const uint4*)(ih + o);
                Bl[(ng + 1) & 1] = *(const uint4*)(il + o);
            }
            mma_unit(D, Ah, Al, Bh[ng & 1], Bl[ng & 1], ng);
            if (ng == 3 && c + 1 < nchunks) loadA(cx, c + 1, Ah, Al);
        }
    }
}

__global__ void __launch_bounds__(NTH, 1)
rnn_mma_kernel(const float* __restrict__ x0, const float* __restrict__ x1,
               const float* __restrict__ x2, const float* __restrict__ b_d,
               float* __restrict__ out) {
    extern __shared__ __align__(1024) unsigned char smem[];
    TileCtx cx;
    cx.sb = smem_u32(smem);
    cx.tid = threadIdx.x;
    cx.lane = cx.tid & 31;
    const int w = cx.tid >> 5;
    cx.m0 = (w & 3) * 32;
    cx.nb = (w >> 2) * 64;
    const int row_base = blockIdx.x * MROWS;

    // init: zero A (h0=0) and Ax; bias col (k=3)=1.0 in Ax-hi; b_d -> smem
    for (int i = cx.tid; i < 131072 / 4; i += NTH) ((uint32_t*)(smem + SM_A))[i] = 0;
    for (int i = cx.tid; i < 8192 / 4; i += NTH) ((uint32_t*)(smem + SM_AX))[i] = 0;
    __syncthreads();
    if (cx.tid < 128) *(unsigned short*)(smem + SM_AX + cx.tid * 32 + 6) = 0x3F80;
    if (cx.tid < 256) ((float*)(smem + SM_BD))[cx.tid] = b_d[cx.tid];

    // x prefetch: thread (row, f) owns one value per step; publish x(t=0)
    const int xrow = cx.tid >> 2, xf = cx.tid & 3;
    const bool xact = (xf < 3);
    const float* xbase = (xf == 0) ? x0 : (xf == 1) ? x1 : x2;
    if (xact) {
        float v = xbase[(size_t)(row_base + xrow) * T_SZ + (T_SZ - 1)];
        __nv_bfloat16 h = __float2bfloat16_rn(v);
        __nv_bfloat16 l = __float2bfloat16_rn(v - __bfloat162float(h));
        *(unsigned short*)(smem + SM_AX + xrow * 32 + xf * 2) = *(unsigned short*)&h;
        *(unsigned short*)(smem + SM_AX + 4096 + xrow * 32 + xf * 2) = *(unsigned short*)&l;
    }
    float xv = 0.0f;
    if (xact) xv = xbase[(size_t)(row_base + xrow) * T_SZ + (T_SZ - 2)];
    __syncthreads();

    float D[2][8][4];
#pragma unroll
    for (int mt = 0; mt < 2; ++mt)
#pragma unroll
        for (int nt = 0; nt < 8; ++nt)
#pragma unroll
            for (int e = 0; e < 4; ++e) D[mt][nt][e] = 0.0f;

#pragma unroll 1
    for (int t = 0; t < T_SZ; ++t) {
        stream_chunks(cx, D, g_U2[0], g_U2[1], 17);   // h@U + x@W_in + b_rnn
        __syncthreads();                              // all A/Ax reads done

        if (xact && t + 1 < T_SZ) {                   // publish next x
            __nv_bfloat16 h = __float2bfloat16_rn(xv);
            __nv_bfloat16 l = __float2bfloat16_rn(xv - __bfloat162float(h));
            *(unsigned short*)(smem + SM_AX + xrow * 32 + xf * 2) = *(unsigned short*)&h;
            *(unsigned short*)(smem + SM_AX + 4096 + xrow * 32 + xf * 2) = *(unsigned short*)&l;
            if (t + 2 < T_SZ)
                xv = xbase[(size_t)(row_base + xrow) * T_SZ + (T_SZ - 3 - t)];
        }
        // epilogue: h = relu(D) -> split -> A (swizzled); zero D
#pragma unroll
        for (int mt = 0; mt < 2; ++mt) {
            int mA = cx.m0 + mt * 16 + (cx.lane >> 2);
#pragma unroll
            for (int nt = 0; nt < 8; ++nt) {
                int n = cx.nb + nt * 8 + 2 * (cx.lane & 3);
#pragma unroll
                for (int half = 0; half < 2; ++half) {
                    int m = mA + half * 8;
                    float v0 = fmaxf(D[mt][nt][2 * half], 0.0f);
                    float v1 = fmaxf(D[mt][nt][2 * half + 1], 0.0f);
                    uint32_t hp;
                    asm("cvt.rn.bf16x2.f32 %0, %1, %2;" : "=r"(hp) : "f"(v1), "f"(v0));
                    float h0 = __uint_as_float(hp << 16);
                    float h1 = __uint_as_float(hp & 0xFFFF0000u);
                    uint32_t lp;
                    asm("cvt.rn.bf16x2.f32 %0, %1, %2;" : "=r"(lp) : "f"(v1 - h1), "f"(v0 - h0));
                    uint32_t off = (uint32_t)(2 * n) ^ ((m & 7) << 4);
                    *(uint32_t*)(smem + SM_A + m * 512 + off) = hp;
                    *(uint32_t*)(smem + SM_A + 65536 + m * 512 + off) = lp;
                }
            }
        }
#pragma unroll
        for (int mt = 0; mt < 2; ++mt)
#pragma unroll
            for (int nt = 0; nt < 8; ++nt)
#pragma unroll
                for (int e = 0; e < 4; ++e) D[mt][nt][e] = 0.0f;
        __syncthreads();                              // A rewrite visible
    }

    // final GEMM: out = hT @ W_d + b_d
    stream_chunks(cx, D, g_W2[0], g_W2[1], 16);
    const float* bd = (const float*)(smem + SM_BD);
#pragma unroll
    for (int mt = 0; mt < 2; ++mt) {
        int mA = cx.m0 + mt * 16 + (cx.lane >> 2);
#pragma unroll
        for (int nt = 0; nt < 8; ++nt) {
            int n = cx.nb + nt * 8 + 2 * (cx.lane & 3);
            float b0 = bd[n], b1 = bd[n + 1];
#pragma unroll
            for (int half = 0; half < 2; ++half) {
                int m = mA + half * 8;
                float2 o = make_float2(D[mt][nt][2 * half] + b0, D[mt][nt][2 * half + 1] + b1);
                *(float2*)(out + (size_t)(row_base + m) * HDIM + n) = o;
            }
        }
    }
}

extern "C" void kernel_launch(void* const* d_in, const int* in_sizes, int n_in,
                              void* d_out, int out_size) {
    (void)in_sizes; (void)n_in; (void)out_size;
    const float* x0    = (const float*)d_in[0];
    const float* x1    = (const float*)d_in[1];
    const float* x2    = (const float*)d_in[2];
    const float* W_in  = (const float*)d_in[3];
    const float* U     = (const float*)d_in[4];
    const float* b_rnn = (const float*)d_in[5];
    const float* W_d   = (const float*)d_in[6];
    const float* b_d   = (const float*)d_in[7];
    float* out = (float*)d_out;

    prep_kernel<<<66, 256>>>(U, W_in, b_rnn, W_d);

    cudaFuncSetAttribute(rnn_mma_kernel,
                         cudaFuncAttributeMaxDynamicSharedMemorySize, SM_TOT);
    rnn_mma_kernel<<<NCTAS, NTH, SM_TOT>>>(x0, x1, x2, b_d, out);
}